// round 15
// baseline (speedup 1.0000x reference)
#include <cuda_runtime.h>
#include <math.h>

#define Bb 2
#define Dd 192
#define Hh 56
#define Ww 56
#define Nn 16
#define Rr 12
#define Kk 4
#define LL (Hh*Ww)      /* 3136 */
#define LLP 3200        /* padded chain length (prefetch overrun) */
#define TP 64           /* positions per prep tile */
#define CH 44           /* R + 2N */
#define CHP 48          /* padded channels */
#define PF 64           /* BC prefetch pad rows */
#define XSTR 196        /* xs smem row stride (words) */
#define DSTR 66         /* dblS row stride */
#define ST 16           /* scan steps per tile */
#define NT (LL/ST)      /* 196 tiles */
#define NPREP 784
#define NSCAN 192

typedef unsigned long long u64;

// ---------------- device scratch ----------------
// g_dz: [sbk(16)][c2(96)][LLP][2 d]  (softplus, delta*u)
// g_BC: [sbk(16)][LL+pad][16 n] = float2(B_n own, C_n cross)
// g_yk: [sbk(16)][c2(96)][LL][2 d]
__device__ float2 g_dz[16*96*LLP*2];
__device__ float2 g_BC[16*(LL+PF)*16];
__device__ float  g_yk[16*96*LL*2];
__device__ float  g_xT[2*Bb*LL*Dd];
__device__ int    g_prep_cnt[8];

__device__ __forceinline__ float ex2(float x) {
    float r; asm("ex2.approx.ftz.f32 %0, %1;" : "=f"(r) : "f"(x)); return r;
}
__device__ __forceinline__ float lg2(float x) {
    float r; asm("lg2.approx.ftz.f32 %0, %1;" : "=f"(r) : "f"(x)); return r;
}
__device__ __forceinline__ u64 ffma2(u64 a, u64 b, u64 c) {
    u64 r; asm("fma.rn.f32x2 %0, %1, %2, %3;" : "=l"(r) : "l"(a), "l"(b), "l"(c)); return r;
}
__device__ __forceinline__ float hadd2(u64 v) {
    float lo, hi; asm("mov.b64 {%0, %1}, %2;" : "=f"(lo), "=f"(hi) : "l"(v)); return lo + hi;
}
#define LOG2E 1.44269504088896340736f
#define LN2   0.69314718055994530942f

__device__ __forceinline__ int tau_of(int k, int pos) {
    int t1 = (pos % Ww) * Hh + pos / Ww;
    switch (k) {
        case 0: return pos;
        case 1: return t1;
        case 2: return LL - 1 - pos;
        default: return LL - 1 - t1;
    }
}

__global__ void zero_cnt_kernel()
{
    if (threadIdx.x < 8) g_prep_cnt[threadIdx.x] = 0;
}

// ================= fused kernel: prep blocks + scan blocks =================
__global__ void __launch_bounds__(256, 2)
fused_kernel(const float* __restrict__ x1, const float* __restrict__ x2,
             const float* __restrict__ pw1, const float* __restrict__ pw2,
             const float* __restrict__ dtw1, const float* __restrict__ dtw2,
             const float* __restrict__ dtb1, const float* __restrict__ dtb2,
             const float* __restrict__ A1, const float* __restrict__ A2)
{
    extern __shared__ float sm[];
    const int bid = blockIdx.x;
    const int t   = threadIdx.x;

    if (bid < NPREP) {
        // ---------------- PREP ----------------
        const int g    = bid / 98;
        const int b    = g >> 2;
        const int k    = g & 3;
        const int rem  = bid - g*98;
        const int s    = rem / 49;
        const int pos0 = (rem - s*49) * TP;

        float* xs   = sm;                    // [TP][XSTR]
        float* Ws   = xs + TP*XSTR;          // [48][192]
        float* dtws = Ws + CHP*Dd;           // [192][12]
        float* bsm  = dtws + Dd*12;          // [192]
        float* dblS = bsm + Dd;              // [48][DSTR]

        const float* x   = s ? x2   : x1;
        const float* pw  = s ? pw2  : pw1;
        const float* dtw = s ? dtw2 : dtw1;
        const float* dtb = s ? dtb2 : dtb1;
        const int sb  = s*2 + b;
        const int sbo = (s^1)*2 + b;

        for (int e = t; e < Dd*(TP/4); e += 256) {
            int d = e >> 4, p4 = (e & 15) * 4;
            float4 v = *(const float4*)&x[(size_t)(b*Dd + d)*LL + pos0 + p4];
            xs[(p4+0)*XSTR + d] = v.x;
            xs[(p4+1)*XSTR + d] = v.y;
            xs[(p4+2)*XSTR + d] = v.z;
            xs[(p4+3)*XSTR + d] = v.w;
        }
        for (int e = t; e < CHP*Dd/4; e += 256) {
            float4 v = (e < CH*Dd/4) ? ((const float4*)pw)[(size_t)k*(CH*Dd/4) + e]
                                     : make_float4(0.f,0.f,0.f,0.f);
            ((float4*)Ws)[e] = v;
        }
        for (int e = t; e < Dd*Rr/4; e += 256)
            ((float4*)dtws)[e] = ((const float4*)dtw)[(size_t)k*(Dd*Rr/4) + e];
        if (t < Dd) bsm[t] = dtb[k*Dd + t];
        __syncthreads();

        if (k == 0) {
            for (int e = t; e < TP*Dd; e += 256) {
                int p = e / Dd, d = e - p*Dd;
                g_xT[(size_t)(sb*LL + pos0 + p)*Dd + d] = xs[p*XSTR + d];
            }
        }

        const int pg = t & 15;
        const int cb = t >> 4;

        {   // GEMM: dbl[c][p] = sum_d W[c][d] * x[d][p]; 4 pos x 3 ch, f32x2 packed
            u64 acc2[4][3];
            #pragma unroll
            for (int i = 0; i < 4; i++)
                #pragma unroll
                for (int j = 0; j < 3; j++) acc2[i][j] = 0ull;

            #pragma unroll 2
            for (int d4 = 0; d4 < Dd; d4 += 4) {
                ulonglong2 w0 = *(const ulonglong2*)&Ws[ cb      *Dd + d4];
                ulonglong2 w1 = *(const ulonglong2*)&Ws[(cb+16) *Dd + d4];
                ulonglong2 w2 = *(const ulonglong2*)&Ws[(cb+32) *Dd + d4];
                #pragma unroll
                for (int i = 0; i < 4; i++) {
                    ulonglong2 xv = *(const ulonglong2*)&xs[(pg + 16*i)*XSTR + d4];
                    acc2[i][0] = ffma2(xv.x, w0.x, acc2[i][0]);
                    acc2[i][0] = ffma2(xv.y, w0.y, acc2[i][0]);
                    acc2[i][1] = ffma2(xv.x, w1.x, acc2[i][1]);
                    acc2[i][1] = ffma2(xv.y, w1.y, acc2[i][1]);
                    acc2[i][2] = ffma2(xv.x, w2.x, acc2[i][2]);
                    acc2[i][2] = ffma2(xv.y, w2.y, acc2[i][2]);
                }
            }
            #pragma unroll
            for (int i = 0; i < 4; i++) {
                dblS[ cb     *DSTR + pg + 16*i] = hadd2(acc2[i][0]);
                dblS[(cb+16) *DSTR + pg + 16*i] = hadd2(acc2[i][1]);
                dblS[(cb+32) *DSTR + pg + 16*i] = hadd2(acc2[i][2]);
            }
        }
        __syncthreads();

        // B(own .x) / C(cross .y) per n, traversal order
        for (int e = t; e < TP*16; e += 256) {
            int p = e >> 4, n = e & 15;
            int tauv = tau_of(k, pos0 + p);
            float* bx = (float*)&g_BC[((size_t)(sb *Kk + k)*(LL+PF) + tauv)*16 + n];
            float* cy = (float*)&g_BC[((size_t)(sbo*Kk + k)*(LL+PF) + tauv)*16 + n];
            bx[0] = dblS[(12+n)*DSTR + p];
            cy[1] = dblS[(28+n)*DSTR + p];
        }

        // dt epilogue: warp-uniform d (broadcast dtw), coalesced STG.128 dz (2 c2 rows)
        {
            const int w    = t >> 5;
            const int lane = t & 31;
            const size_t sbk96 = (size_t)(sb*Kk + k)*96;
            #pragma unroll
            for (int cc = 0; cc < 6; cc++) {
                const int c  = w + cc*8;          // 4-d chunk -> c2 rows {2c, 2c+1}
                const int d0 = c*4;
                #pragma unroll
                for (int ph = 0; ph < 2; ph++) {
                    const int p = ph*32 + lane;
                    const int tauv = tau_of(k, pos0 + p);
                    float rr[12];
                    #pragma unroll
                    for (int r = 0; r < 12; r++) rr[r] = dblS[r*DSTR + p];
                    float o8[8];
                    #pragma unroll
                    for (int q = 0; q < 4; q++) {
                        const int d = d0 + q;
                        const float4* dwp = (const float4*)&dtws[d*12];
                        const float4 wa = dwp[0], wb = dwp[1], wc = dwp[2];
                        float a = bsm[d];
                        a = fmaf(wa.x, rr[0], a);  a = fmaf(wa.y, rr[1], a);
                        a = fmaf(wa.z, rr[2], a);  a = fmaf(wa.w, rr[3], a);
                        a = fmaf(wb.x, rr[4], a);  a = fmaf(wb.y, rr[5], a);
                        a = fmaf(wb.z, rr[6], a);  a = fmaf(wb.w, rr[7], a);
                        a = fmaf(wc.x, rr[8], a);  a = fmaf(wc.y, rr[9], a);
                        a = fmaf(wc.z, rr[10], a); a = fmaf(wc.w, rr[11], a);
                        float em = ex2(-fabsf(a) * LOG2E);
                        float sp = fmaxf(a, 0.f) + lg2(1.f + em) * LN2;
                        float z  = sp * xs[p*XSTR + d];
                        o8[q*2] = sp; o8[q*2+1] = z;
                    }
                    *(float4*)&g_dz[((sbk96 + 2*c    )*LLP + tauv)*2] = make_float4(o8[0], o8[1], o8[2], o8[3]);
                    *(float4*)&g_dz[((sbk96 + 2*c + 1)*LLP + tauv)*2] = make_float4(o8[4], o8[5], o8[6], o8[7]);
                }
            }
        }

        __threadfence();
        __syncthreads();
        if (t == 0) atomicAdd(&g_prep_cnt[g], 1);
        return;
    }

    // ---------------- SCAN: 8 warps, 2 chains/warp, 1 ex2/step ----------------
    {
        const int sid  = bid - NPREP;
        const int g    = sid / 24;
        const int b    = g >> 2;
        const int k    = g & 3;
        const int rem  = sid - g*24;
        const int s    = rem / 12;
        const int blk  = rem - s*12;
        const int sb   = s*2 + b;

        if (t == 0) {
            volatile int* c = (volatile int*)&g_prep_cnt[g];
            while (*c < 98) __nanosleep(128);
        }
        __syncthreads();
        __threadfence();

        float2* s_dz = (float2*)sm;            // [8 w][4 slots][16 t][2 d]  8 KB
        float2* s_bc = (float2*)(sm + 2048);   // [8 w][4 slots][16 t][16 n] 64 KB

        const int w    = t >> 5;
        const int lane = t & 31;
        const int dl = lane >> 4, n = lane & 15;
        const int c2 = blk*8 + w;              // this warp's 2-chain row
        const int d  = c2*2 + dl;

        const float* Alog = s ? A2 : A1;
        const float a = -__expf(Alog[(k*Dd + d)*Nn + n]) * LOG2E;

        const size_t sbk96 = (size_t)(sb*Kk + k)*96;
        const size_t bcrow = (size_t)(sb*Kk + k)*(LL+PF);
        const float2* dz_src = g_dz + (sbk96 + c2)*LLP*2;      // 2 float2 per step
        const float2* bc_src = g_BC + bcrow*16;                // 16 float2 per step
        float* yp = g_yk + (sbk96 + c2)*(size_t)LL*2 + dl;

        // bit-reversed step ownership after 4 reduce-scatter rounds
        const int s0 = ((n & 1) << 3) | (((n >> 1) & 1) << 2) | (((n >> 2) & 1) << 1) | ((n >> 3) & 1);

        #define LOAD_TILE(slot, tile) do {                                                       \
            if (lane < 16) {                                                                     \
                unsigned za = (unsigned)__cvta_generic_to_shared(                                \
                    &s_dz[((w*4+(slot))*16 + lane)*2]);                                          \
                asm volatile("cp.async.cg.shared.global [%0], [%1], 16;" ::                      \
                             "r"(za), "l"(dz_src + (size_t)((tile)*ST + lane)*2));               \
            }                                                                                    \
            _Pragma("unroll")                                                                    \
            for (int q = 0; q < 4; q++) {                                                        \
                unsigned ba = (unsigned)__cvta_generic_to_shared(                                \
                    &s_bc[(w*4+(slot))*256 + (q*32 + lane)*2]);                                  \
                asm volatile("cp.async.cg.shared.global [%0], [%1], 16;" ::                      \
                             "r"(ba), "l"(bc_src + (size_t)(tile)*256 + (q*32 + lane)*2));       \
            }                                                                                    \
            asm volatile("cp.async.commit_group;");                                              \
        } while (0)

        LOAD_TILE(0, 0);
        LOAD_TILE(1, 1);
        LOAD_TILE(2, 2);

        float h = 0.f;
        for (int it = 0; it < NT; it++) {
            const int slot = it & 3;
            const int tt = it * ST;
            asm volatile("cp.async.wait_group 2;");
            __syncwarp();
            LOAD_TILE((it + 3) & 3, it + 3);   // pads cover tail tiles

            float yy[16];
            #pragma unroll
            for (int hb = 0; hb < 2; hb++) {
                float2 dzr[8], bcr[8];
                #pragma unroll
                for (int j = 0; j < 8; j++) {
                    dzr[j] = s_dz[((w*4+slot)*16 + hb*8 + j)*2 + dl];
                    bcr[j] = s_bc[(w*4+slot)*256 + (hb*8 + j)*16 + n];
                }
                float e[8];
                #pragma unroll
                for (int j = 0; j < 8; j++) e[j] = ex2(dzr[j].x * a);
                #pragma unroll
                for (int j = 0; j < 8; j++) {
                    h = fmaf(e[j], h, dzr[j].y * bcr[j].x);
                    yy[hb*8 + j] = h * bcr[j].y;
                }
            }
            // 4-round reduce-scatter over the 16 n-lanes (dl halves disjoint)
            #pragma unroll
            for (int j = 0; j < 8; j++) {
                float send = (n & 1) ? yy[j] : yy[8 + j];
                float recv = __shfl_xor_sync(0xffffffffu, send, 1);
                yy[j] = ((n & 1) ? yy[8 + j] : yy[j]) + recv;
            }
            #pragma unroll
            for (int j = 0; j < 4; j++) {
                float send = (n & 2) ? yy[j] : yy[4 + j];
                float recv = __shfl_xor_sync(0xffffffffu, send, 2);
                yy[j] = ((n & 2) ? yy[4 + j] : yy[j]) + recv;
            }
            #pragma unroll
            for (int j = 0; j < 2; j++) {
                float send = (n & 4) ? yy[j] : yy[2 + j];
                float recv = __shfl_xor_sync(0xffffffffu, send, 4);
                yy[j] = ((n & 4) ? yy[2 + j] : yy[j]) + recv;
            }
            {
                float send = (n & 8) ? yy[0] : yy[1];
                float recv = __shfl_xor_sync(0xffffffffu, send, 8);
                float y0 = ((n & 8) ? yy[1] : yy[0]) + recv;
                yp[(size_t)(tt + s0)*2] = y0;   // warp covers 128 B window
            }
        }
        asm volatile("cp.async.wait_group 0;");
        #undef LOAD_TILE
    }
}

// ---------------- merge (sum k) + D*u + LayerNorm ----------------
__global__ void merge_ln_kernel(const float* __restrict__ D1s, const float* __restrict__ D2s,
                                const float* __restrict__ lnw, const float* __restrict__ lnb,
                                float* __restrict__ out)
{
    __shared__ float red[6];
    const int rid = blockIdx.x;
    const int sb = rid / LL, pos = rid % LL;
    const int s = sb >> 1;
    const int d = threadIdx.x;
    const float* Ds = s ? D2s : D1s;

    const int t1 = (pos % Ww) * Hh + pos / Ww;
    const size_t kb = (size_t)(sb*Kk)*96;
    const int c2 = d >> 1, dr = d & 1;

    #define YIDX(KK, TT) (((kb + (KK)*96 + c2)*(size_t)LL + (TT))*2 + dr)
    float v = g_yk[YIDX(0, pos)]
            + g_yk[YIDX(1, t1)]
            + g_yk[YIDX(2, LL-1-pos)]
            + g_yk[YIDX(3, LL-1-t1)];
    #undef YIDX
    const float Dsum = Ds[d] + Ds[Dd + d] + Ds[2*Dd + d] + Ds[3*Dd + d];
    v = fmaf(Dsum, g_xT[(size_t)(sb*LL + pos)*Dd + d], v);

    float tsum = v;
    #pragma unroll
    for (int o = 16; o; o >>= 1) tsum += __shfl_xor_sync(0xffffffffu, tsum, o);
    if ((d & 31) == 0) red[d >> 5] = tsum;
    __syncthreads();
    const float mu = (red[0]+red[1]+red[2]+red[3]+red[4]+red[5]) * (1.f/192.f);
    const float dv = v - mu;
    __syncthreads();
    float q = dv*dv;
    #pragma unroll
    for (int o = 16; o; o >>= 1) q += __shfl_xor_sync(0xffffffffu, q, o);
    if ((d & 31) == 0) red[d >> 5] = q;
    __syncthreads();
    const float var = (red[0]+red[1]+red[2]+red[3]+red[4]+red[5]) * (1.f/192.f);

    out[rid*Dd + d] = dv * rsqrtf(var + 1e-5f) * lnw[d] + lnb[d];
}

// ---------------- launch ----------------
extern "C" void kernel_launch(void* const* d_in, const int* in_sizes, int n_in,
                              void* d_out, int out_size)
{
    const float* x1   = (const float*)d_in[0];
    const float* x2   = (const float*)d_in[1];
    const float* pw1  = (const float*)d_in[2];
    const float* pw2  = (const float*)d_in[3];
    const float* dtw1 = (const float*)d_in[4];
    const float* dtw2 = (const float*)d_in[5];
    const float* dtb1 = (const float*)d_in[6];
    const float* dtb2 = (const float*)d_in[7];
    const float* A1   = (const float*)d_in[8];
    const float* A2   = (const float*)d_in[9];
    const float* D1s  = (const float*)d_in[10];
    const float* D2s  = (const float*)d_in[11];
    const float* lnw  = (const float*)d_in[12];
    const float* lnb  = (const float*)d_in[13];
    float* out = (float*)d_out;

    const int smem = (TP*XSTR + CHP*Dd + Dd*12 + Dd + CHP*DSTR) * (int)sizeof(float); // 109,696 B
    cudaFuncSetAttribute(fused_kernel, cudaFuncAttributeMaxDynamicSharedMemorySize, smem);

    zero_cnt_kernel<<<1, 32>>>();
    fused_kernel<<<NPREP + NSCAN, 256, smem>>>(x1, x2, pw1, pw2, dtw1, dtw2,
                                               dtb1, dtb2, A1, A2);
    merge_ln_kernel<<<2*Bb*LL, Dd>>>(D1s, D2s, lnw, lnb, out);
}

// round 16
// speedup vs baseline: 1.1041x; 1.1041x over previous
#include <cuda_runtime.h>
#include <math.h>

#define Bb 2
#define Dd 192
#define Hh 56
#define Ww 56
#define Nn 16
#define Rr 12
#define Kk 4
#define LL (Hh*Ww)      /* 3136 */
#define LLP 3200        /* padded chain length (prefetch overrun) */
#define TP 64           /* positions per prep tile */
#define CH 44           /* R + 2N */
#define CHP 48          /* padded channels */
#define PF 64           /* BC prefetch pad rows */
#define XSTR 196        /* xs smem row stride (words) */
#define DSTR 66         /* dblS row stride */
#define ST 16           /* scan steps per tile */
#define NT (LL/ST)      /* 196 tiles */

typedef unsigned long long u64;

// ---------------- device scratch ----------------
// g_dz: [sbk(16)][c2(96)][LLP][2 d]  (softplus, delta*u)
// g_BC: [sbk(16)][LL+PF][16 n] = float2(B_n own, C_n cross)
// g_yk: [sbk(16)][c2(96)][LL][2 d]
__device__ float2 g_dz[16*96*LLP*2];
__device__ float2 g_BC[16*(LL+PF)*16];
__device__ float  g_yk[16*96*LL*2];
__device__ float  g_xT[2*Bb*LL*Dd];

__device__ __forceinline__ float ex2(float x) {
    float r; asm("ex2.approx.ftz.f32 %0, %1;" : "=f"(r) : "f"(x)); return r;
}
__device__ __forceinline__ float lg2(float x) {
    float r; asm("lg2.approx.ftz.f32 %0, %1;" : "=f"(r) : "f"(x)); return r;
}
__device__ __forceinline__ u64 ffma2(u64 a, u64 b, u64 c) {
    u64 r; asm("fma.rn.f32x2 %0, %1, %2, %3;" : "=l"(r) : "l"(a), "l"(b), "l"(c)); return r;
}
__device__ __forceinline__ float hadd2(u64 v) {
    float lo, hi; asm("mov.b64 {%0, %1}, %2;" : "=f"(lo), "=f"(hi) : "l"(v)); return lo + hi;
}
#define LOG2E 1.44269504088896340736f
#define LN2   0.69314718055994530942f

__device__ __forceinline__ int tau_of(int k, int pos) {
    int t1 = (pos % Ww) * Hh + pos / Ww;
    switch (k) {
        case 0: return pos;
        case 1: return t1;
        case 2: return LL - 1 - pos;
        default: return LL - 1 - t1;
    }
}

// ---------------- kernel 1: projections + precompute ----------------
__global__ void __launch_bounds__(256, 2)
prep_kernel(const float* __restrict__ x1, const float* __restrict__ x2,
            const float* __restrict__ pw1, const float* __restrict__ pw2,
            const float* __restrict__ dtw1, const float* __restrict__ dtw2,
            const float* __restrict__ dtb1, const float* __restrict__ dtb2)
{
    extern __shared__ float sm[];
    const int t = threadIdx.x;
    const int pos0 = blockIdx.x * TP;
    const int k    = blockIdx.y;
    const int sbz  = blockIdx.z;
    const int s    = sbz >> 1, b = sbz & 1;

    float* xs   = sm;                    // [TP][XSTR]
    float* Ws   = xs + TP*XSTR;          // [48][192]
    float* dtws = Ws + CHP*Dd;           // [192][12]
    float* bsm  = dtws + Dd*12;          // [192]
    float* dblS = bsm + Dd;              // [48][DSTR]

    const float* x   = s ? x2   : x1;
    const float* pw  = s ? pw2  : pw1;
    const float* dtw = s ? dtw2 : dtw1;
    const float* dtb = s ? dtb2 : dtb1;
    const int sb  = s*2 + b;
    const int sbo = (s^1)*2 + b;

    for (int e = t; e < Dd*(TP/4); e += 256) {
        int d = e >> 4, p4 = (e & 15) * 4;
        float4 v = *(const float4*)&x[(size_t)(b*Dd + d)*LL + pos0 + p4];
        xs[(p4+0)*XSTR + d] = v.x;
        xs[(p4+1)*XSTR + d] = v.y;
        xs[(p4+2)*XSTR + d] = v.z;
        xs[(p4+3)*XSTR + d] = v.w;
    }
    for (int e = t; e < CHP*Dd/4; e += 256) {
        float4 v = (e < CH*Dd/4) ? ((const float4*)pw)[(size_t)k*(CH*Dd/4) + e]
                                 : make_float4(0.f,0.f,0.f,0.f);
        ((float4*)Ws)[e] = v;
    }
    for (int e = t; e < Dd*Rr/4; e += 256)
        ((float4*)dtws)[e] = ((const float4*)dtw)[(size_t)k*(Dd*Rr/4) + e];
    if (t < Dd) bsm[t] = dtb[k*Dd + t];
    __syncthreads();

    if (k == 0) {
        for (int e = t; e < TP*Dd; e += 256) {
            int p = e / Dd, d = e - p*Dd;
            g_xT[(size_t)(sb*LL + pos0 + p)*Dd + d] = xs[p*XSTR + d];
        }
    }

    const int pg = t & 15;
    const int cb = t >> 4;

    {   // GEMM: dbl[c][p] = sum_d W[c][d] * x[d][p]; 4 pos x 3 ch, f32x2 packed
        u64 acc2[4][3];
        #pragma unroll
        for (int i = 0; i < 4; i++)
            #pragma unroll
            for (int j = 0; j < 3; j++) acc2[i][j] = 0ull;

        #pragma unroll 2
        for (int d4 = 0; d4 < Dd; d4 += 4) {
            ulonglong2 w0 = *(const ulonglong2*)&Ws[ cb      *Dd + d4];
            ulonglong2 w1 = *(const ulonglong2*)&Ws[(cb+16) *Dd + d4];
            ulonglong2 w2 = *(const ulonglong2*)&Ws[(cb+32) *Dd + d4];
            #pragma unroll
            for (int i = 0; i < 4; i++) {
                ulonglong2 xv = *(const ulonglong2*)&xs[(pg + 16*i)*XSTR + d4];
                acc2[i][0] = ffma2(xv.x, w0.x, acc2[i][0]);
                acc2[i][0] = ffma2(xv.y, w0.y, acc2[i][0]);
                acc2[i][1] = ffma2(xv.x, w1.x, acc2[i][1]);
                acc2[i][1] = ffma2(xv.y, w1.y, acc2[i][1]);
                acc2[i][2] = ffma2(xv.x, w2.x, acc2[i][2]);
                acc2[i][2] = ffma2(xv.y, w2.y, acc2[i][2]);
            }
        }
        #pragma unroll
        for (int i = 0; i < 4; i++) {
            dblS[ cb     *DSTR + pg + 16*i] = hadd2(acc2[i][0]);
            dblS[(cb+16) *DSTR + pg + 16*i] = hadd2(acc2[i][1]);
            dblS[(cb+32) *DSTR + pg + 16*i] = hadd2(acc2[i][2]);
        }
    }
    __syncthreads();

    // B(own .x) / C(cross .y) per n, traversal order
    for (int e = t; e < TP*16; e += 256) {
        int p = e >> 4, n = e & 15;
        int tauv = tau_of(k, pos0 + p);
        float* bx = (float*)&g_BC[((size_t)(sb *Kk + k)*(LL+PF) + tauv)*16 + n];
        float* cy = (float*)&g_BC[((size_t)(sbo*Kk + k)*(LL+PF) + tauv)*16 + n];
        bx[0] = dblS[(12+n)*DSTR + p];
        cy[1] = dblS[(28+n)*DSTR + p];
    }

    // dt epilogue: warp-uniform d (broadcast dtw), coalesced STG.128 dz (2 c2 rows)
    {
        const int w    = t >> 5;
        const int lane = t & 31;
        const size_t sbk96 = (size_t)(sb*Kk + k)*96;
        #pragma unroll
        for (int cc = 0; cc < 6; cc++) {
            const int c  = w + cc*8;
            const int d0 = c*4;
            #pragma unroll
            for (int ph = 0; ph < 2; ph++) {
                const int p = ph*32 + lane;
                const int tauv = tau_of(k, pos0 + p);
                float rr[12];
                #pragma unroll
                for (int r = 0; r < 12; r++) rr[r] = dblS[r*DSTR + p];
                float o8[8];
                #pragma unroll
                for (int q = 0; q < 4; q++) {
                    const int d = d0 + q;
                    const float4* dwp = (const float4*)&dtws[d*12];
                    const float4 wa = dwp[0], wb = dwp[1], wc = dwp[2];
                    float a = bsm[d];
                    a = fmaf(wa.x, rr[0], a);  a = fmaf(wa.y, rr[1], a);
                    a = fmaf(wa.z, rr[2], a);  a = fmaf(wa.w, rr[3], a);
                    a = fmaf(wb.x, rr[4], a);  a = fmaf(wb.y, rr[5], a);
                    a = fmaf(wb.z, rr[6], a);  a = fmaf(wb.w, rr[7], a);
                    a = fmaf(wc.x, rr[8], a);  a = fmaf(wc.y, rr[9], a);
                    a = fmaf(wc.z, rr[10], a); a = fmaf(wc.w, rr[11], a);
                    float em = ex2(-fabsf(a) * LOG2E);
                    float sp = fmaxf(a, 0.f) + lg2(1.f + em) * LN2;
                    float z  = sp * xs[p*XSTR + d];
                    o8[q*2] = sp; o8[q*2+1] = z;
                }
                *(float4*)&g_dz[((sbk96 + 2*c    )*LLP + tauv)*2] = make_float4(o8[0], o8[1], o8[2], o8[3]);
                *(float4*)&g_dz[((sbk96 + 2*c + 1)*LLP + tauv)*2] = make_float4(o8[4], o8[5], o8[6], o8[7]);
            }
        }
    }
}

// ---------------- kernel 2: scan: 4 warps/block, 2 chains/warp, 1 ex2/step ----------------
// grid (24, K, SB) = 384 blocks; static 36 KB smem -> deep co-residency, single wave.
__global__ void __launch_bounds__(128) scan_kernel(const float* __restrict__ A1,
                                                   const float* __restrict__ A2)
{
    __shared__ float2 s_dz[4][4][ST][2];    //  4 KB
    __shared__ float2 s_bc[4][4][ST][16];   // 32 KB

    const int t    = threadIdx.x;
    const int w    = t >> 5;
    const int lane = t & 31;
    const int dl = lane >> 4, n = lane & 15;
    const int k  = blockIdx.y;
    const int sb = blockIdx.z;
    const int s  = sb >> 1;
    const int c2 = blockIdx.x*4 + w;        // this warp's 2-chain row
    const int d  = c2*2 + dl;

    const float* Alog = s ? A2 : A1;
    const float a = -__expf(Alog[(k*Dd + d)*Nn + n]) * LOG2E;

    const size_t sbk96 = (size_t)(sb*Kk + k)*96;
    const size_t bcrow = (size_t)(sb*Kk + k)*(LL+PF);
    const float2* dz_src = g_dz + (sbk96 + c2)*LLP*2;      // 2 float2 per step
    const float2* bc_src = g_BC + bcrow*16;                // 16 float2 per step
    float* yp = g_yk + (sbk96 + c2)*(size_t)LL*2 + dl;

    // bit-reversed step ownership after 4 reduce-scatter rounds
    const int s0 = ((n & 1) << 3) | (((n >> 1) & 1) << 2) | (((n >> 2) & 1) << 1) | ((n >> 3) & 1);

    #define LOAD_TILE(slot, tile) do {                                                       \
        if (lane < 16) {                                                                     \
            unsigned za = (unsigned)__cvta_generic_to_shared(&s_dz[w][slot][lane][0]);       \
            asm volatile("cp.async.cg.shared.global [%0], [%1], 16;" ::                      \
                         "r"(za), "l"(dz_src + (size_t)((tile)*ST + lane)*2));               \
        }                                                                                    \
        _Pragma("unroll")                                                                    \
        for (int q = 0; q < 4; q++) {                                                        \
            unsigned ba = (unsigned)__cvta_generic_to_shared(                                \
                &((float2*)s_bc[w][slot])[(q*32 + lane)*2]);                                 \
            asm volatile("cp.async.cg.shared.global [%0], [%1], 16;" ::                      \
                         "r"(ba), "l"(bc_src + (size_t)(tile)*256 + (q*32 + lane)*2));       \
        }                                                                                    \
        asm volatile("cp.async.commit_group;");                                              \
    } while (0)

    LOAD_TILE(0, 0);
    LOAD_TILE(1, 1);
    LOAD_TILE(2, 2);

    float h = 0.f;
    for (int it = 0; it < NT; it++) {
        const int slot = it & 3;
        const int tt = it * ST;
        asm volatile("cp.async.wait_group 2;");
        __syncwarp();
        LOAD_TILE((it + 3) & 3, it + 3);   // pads cover tail tiles

        float yy[16];
        #pragma unroll
        for (int hb = 0; hb < 2; hb++) {
            float2 dzr[8], bcr[8];
            #pragma unroll
            for (int j = 0; j < 8; j++) {
                dzr[j] = s_dz[w][slot][hb*8 + j][dl];
                bcr[j] = s_bc[w][slot][hb*8 + j][n];
            }
            float e[8];
            #pragma unroll
            for (int j = 0; j < 8; j++) e[j] = ex2(dzr[j].x * a);
            #pragma unroll
            for (int j = 0; j < 8; j++) {
                h = fmaf(e[j], h, dzr[j].y * bcr[j].x);
                yy[hb*8 + j] = h * bcr[j].y;
            }
        }
        // 4-round reduce-scatter over the 16 n-lanes (dl halves disjoint)
        #pragma unroll
        for (int j = 0; j < 8; j++) {
            float send = (n & 1) ? yy[j] : yy[8 + j];
            float recv = __shfl_xor_sync(0xffffffffu, send, 1);
            yy[j] = ((n & 1) ? yy[8 + j] : yy[j]) + recv;
        }
        #pragma unroll
        for (int j = 0; j < 4; j++) {
            float send = (n & 2) ? yy[j] : yy[4 + j];
            float recv = __shfl_xor_sync(0xffffffffu, send, 2);
            yy[j] = ((n & 2) ? yy[4 + j] : yy[j]) + recv;
        }
        #pragma unroll
        for (int j = 0; j < 2; j++) {
            float send = (n & 4) ? yy[j] : yy[2 + j];
            float recv = __shfl_xor_sync(0xffffffffu, send, 4);
            yy[j] = ((n & 4) ? yy[2 + j] : yy[j]) + recv;
        }
        {
            float send = (n & 8) ? yy[0] : yy[1];
            float recv = __shfl_xor_sync(0xffffffffu, send, 8);
            float y0 = ((n & 8) ? yy[1] : yy[0]) + recv;
            yp[(size_t)(tt + s0)*2] = y0;   // warp covers a 128 B window
        }
    }
    asm volatile("cp.async.wait_group 0;");
    #undef LOAD_TILE
}

// ---------------- kernel 3: merge (sum k) + D*u + LayerNorm ----------------
__global__ void merge_ln_kernel(const float* __restrict__ D1s, const float* __restrict__ D2s,
                                const float* __restrict__ lnw, const float* __restrict__ lnb,
                                float* __restrict__ out)
{
    __shared__ float red[6];
    const int rid = blockIdx.x;
    const int sb = rid / LL, pos = rid % LL;
    const int s = sb >> 1;
    const int d = threadIdx.x;
    const float* Ds = s ? D2s : D1s;

    const int t1 = (pos % Ww) * Hh + pos / Ww;
    const size_t kb = (size_t)(sb*Kk)*96;
    const int c2 = d >> 1, dr = d & 1;

    #define YIDX(KK, TT) (((kb + (KK)*96 + c2)*(size_t)LL + (TT))*2 + dr)
    float v = g_yk[YIDX(0, pos)]
            + g_yk[YIDX(1, t1)]
            + g_yk[YIDX(2, LL-1-pos)]
            + g_yk[YIDX(3, LL-1-t1)];
    #undef YIDX
    const float Dsum = Ds[d] + Ds[Dd + d] + Ds[2*Dd + d] + Ds[3*Dd + d];
    v = fmaf(Dsum, g_xT[(size_t)(sb*LL + pos)*Dd + d], v);

    float tsum = v;
    #pragma unroll
    for (int o = 16; o; o >>= 1) tsum += __shfl_xor_sync(0xffffffffu, tsum, o);
    if ((d & 31) == 0) red[d >> 5] = tsum;
    __syncthreads();
    const float mu = (red[0]+red[1]+red[2]+red[3]+red[4]+red[5]) * (1.f/192.f);
    const float dv = v - mu;
    __syncthreads();
    float q = dv*dv;
    #pragma unroll
    for (int o = 16; o; o >>= 1) q += __shfl_xor_sync(0xffffffffu, q, o);
    if ((d & 31) == 0) red[d >> 5] = q;
    __syncthreads();
    const float var = (red[0]+red[1]+red[2]+red[3]+red[4]+red[5]) * (1.f/192.f);

    out[rid*Dd + d] = dv * rsqrtf(var + 1e-5f) * lnw[d] + lnb[d];
}

// ---------------- launch ----------------
extern "C" void kernel_launch(void* const* d_in, const int* in_sizes, int n_in,
                              void* d_out, int out_size)
{
    const float* x1   = (const float*)d_in[0];
    const float* x2   = (const float*)d_in[1];
    const float* pw1  = (const float*)d_in[2];
    const float* pw2  = (const float*)d_in[3];
    const float* dtw1 = (const float*)d_in[4];
    const float* dtw2 = (const float*)d_in[5];
    const float* dtb1 = (const float*)d_in[6];
    const float* dtb2 = (const float*)d_in[7];
    const float* A1   = (const float*)d_in[8];
    const float* A2   = (const float*)d_in[9];
    const float* D1s  = (const float*)d_in[10];
    const float* D2s  = (const float*)d_in[11];
    const float* lnw  = (const float*)d_in[12];
    const float* lnb  = (const float*)d_in[13];
    float* out = (float*)d_out;

    const int smem = (TP*XSTR + CHP*Dd + Dd*12 + Dd + CHP*DSTR) * (int)sizeof(float); // 109,696 B
    cudaFuncSetAttribute(prep_kernel, cudaFuncAttributeMaxDynamicSharedMemorySize, smem);

    prep_kernel<<<dim3(LL/TP, Kk, 4), 256, smem>>>(x1, x2, pw1, pw2, dtw1, dtw2, dtb1, dtb2);
    scan_kernel<<<dim3(24, Kk, 2*Bb), 128>>>(A1, A2);
    merge_ln_kernel<<<2*Bb*LL, Dd>>>(D1s, D2s, lnw, lnb, out);
}